// round 17
// baseline (speedup 1.0000x reference)
#include <cuda_runtime.h>
#include <cuda_bf16.h>
#include <cstdint>

// Problem constants (fixed by the dataset): B=64, T=12, C=64, SIDE=32, S2=1024.
#define PB   64
#define PT   12
#define PC   64
#define PS2  1024
#define ROWS (PB * PC)            // 4096 (b,c) rows in the last-T slice

#define RPB    4                  // rows per block
#define GRIDM  (ROWS / RPB)       // 1024 blocks
#define NSHARD 16                 // mask atomic shards (1024/16 = 64 RMW per address)

// Persistent scratch (module-load zeroed; the last-arriving block re-zeroes it
// each launch => every call identical => graph-replay deterministic).
__device__ unsigned g_maskpad[NSHARD * 32 * 64];  // word (k,i) at (k*32+i)*64
__device__ int      g_c1;                         // completion counter

// Speculative apply + true-mask reduce + last-block verification/repair.
//   guess:  cell s is empty  <=>  s even   (forced by reference's cell_keep)
//   out[row,s] = d[row,s] + (s even ? d[row,poi[s]] : 0)   written immediately
//   true mask published to shards; LAST block verifies, repairs if ever wrong.
__global__ void __launch_bounds__(256, 8)
main_kernel(const float* __restrict__ d, const int* __restrict__ m,
            const int* __restrict__ poi_words, float* __restrict__ out) {
    __shared__ float    rs[RPB][PS2];     // 16 KB staged d rows
    __shared__ unsigned smask[32];        // block-partial 1024-bit nonzero mask
    __shared__ int      sh_odd, sh_last;
    __shared__ unsigned nz[32];           // (tail) combined true mask

    const int t = threadIdx.x;            // 0..255
    const int g = blockIdx.x;             // 0..1023
    const int row0 = g * RPB;
    const int b  = row0 >> 6;
    const int cc = row0 & 63;
    const size_t base = ((size_t)(b * PT + (PT - 1)) * PC + cc) * PS2;

    if (t == 0) { sh_odd = 0; sh_last = 0; }
    if (t < 32) smask[t] = 0;

    // ---- TRUE mask reduce over this block's 4 m rows (cells 4t..4t+3) ----
    const int* msrc = m + base;
    int4 acc = make_int4(0, 0, 0, 0);
#pragma unroll
    for (int r = 0; r < RPB; r++) {
        const int4 v = *(const int4*)(msrc + r * PS2 + 4 * t);
        acc.x |= v.x; acc.y |= v.y; acc.z |= v.z; acc.w |= v.w;
    }

    // ---- poi decode (every block; dtype auto-detect: JAX silently narrows
    // jnp.int64 -> int32). First 1024 words safe for both dtypes; int64
    // little-endian with values < 1024 => all odd words zero.
    const int4 w  = ((const int4*)poi_words)[t];
    const int4 p0 = ((const int4*)poi_words)[2 * t];
    const int4 p1 = ((const int4*)poi_words)[2 * t + 1];
    if (w.y | w.w) atomicOr(&sh_odd, 1);

    // ---- stage this block's 4 d rows into smem ----
    const float* dsrc = d + base;
    float4 v[RPB];
#pragma unroll
    for (int r = 0; r < RPB; r++)
        v[r] = *(const float4*)(dsrc + r * PS2 + 4 * t);
#pragma unroll
    for (int r = 0; r < RPB; r++)
        ((float4*)rs[r])[t] = v[r];

    __syncthreads();                      // rs staged, sh_odd + smask ready
    const int4 pi = sh_odd ? w : make_int4(p0.x, p0.z, p1.x, p1.z);

    const unsigned nib = (acc.x ? 1u : 0u) | (acc.y ? 2u : 0u)
                       | (acc.z ? 4u : 0u) | (acc.w ? 8u : 0u);
    if (nib) atomicOr(&smask[t >> 3], nib << ((t & 7) * 4));
    __syncthreads();                      // smask final
    if (t < 32 && smask[t])
        atomicOr(&g_maskpad[(((g & (NSHARD - 1)) * 32 + t) << 6)], smask[t]);

    // ---- speculative output: even cells (4t, 4t+2) get the compensation ----
#pragma unroll
    for (int r = 0; r < RPB; r++) {
        float4 x = v[r];
        x.x += rs[r][pi.x];               // cell 4t   (even -> guessed empty)
        x.z += rs[r][pi.z];               // cell 4t+2 (even -> guessed empty)
        ((float4*)(out + (size_t)(row0 + r) * PS2))[t] = x;
    }

    // ---- completion: last-arriving block verifies the guess ----
    if (t == 0) {
        __threadfence();                  // publish stores + shard flushes
        if (atomicAdd(&g_c1, 1) == GRIDM - 1) sh_last = 1;
    }
    __syncthreads();
    if (!sh_last) return;

    // ======== TAIL (one block; all other blocks' work already visible) ======
    __threadfence();                      // acquire
    if (t < 32) {
        unsigned x = 0;
#pragma unroll
        for (int k = 0; k < NSHARD; k++)
            x |= ((const volatile unsigned*)g_maskpad)[((k * 32 + t) << 6)];
        nz[t] = x;
    }
    __syncthreads();
    // guess: empty == even cell. actual: empty == (nz bit == 0).
    // mismatch word = nz ^ 0xAAAAAAAA  (odd cells should be nonzero, even zero)
    __shared__ int sh_any;
    if (t == 0) sh_any = 0;
    __syncthreads();
    if (t < 32 && (nz[t] ^ 0xAAAAAAAAu)) atomicOr(&sh_any, 1);
    __syncthreads();

    if (sh_any) {
        // slow path (never taken for this distribution; correctness insurance):
        // repair every mismatched cell of every row straight from d.
        __shared__ unsigned mismw[32];
        __shared__ int spoi[PS2];
        if (t < 32) mismw[t] = nz[t] ^ 0xAAAAAAAAu;
        {
            const int4 q0 = ((const int4*)poi_words)[2 * t];
            const int4 q1 = ((const int4*)poi_words)[2 * t + 1];
            ((int4*)spoi)[t] = sh_odd ? ((const int4*)poi_words)[t]
                                      : make_int4(q0.x, q0.z, q1.x, q1.z);
        }
        __syncthreads();
        for (int R = 0; R < ROWS; R++) {
            const int bb = R >> 6, c = R & 63;
            const float* drow = d + ((size_t)(bb * PT + (PT - 1)) * PC + c) * PS2;
            float* orow = out + (size_t)R * PS2;
            for (int s = t; s < PS2; s += 256) {
                if ((mismw[s >> 5] >> (s & 31)) & 1u) {
                    const bool empty = !((nz[s >> 5] >> (s & 31)) & 1u);
                    orow[s] = drow[s] + (empty ? drow[spoi[s]] : 0.0f);
                }
            }
        }
    }

    // reset scratch for the next (graph) replay
    for (int i = t; i < NSHARD * 32; i += 256) g_maskpad[i << 6] = 0;
    if (t == 0) { g_c1 = 0; __threadfence(); }
}

extern "C" void kernel_launch(void* const* d_in, const int* in_sizes, int n_in,
                              void* d_out, int out_size) {
    const float* d   = (const float*)d_in[0];
    const int*   m   = (const int*)d_in[1];
    const int*   poi = (const int*)d_in[2];   // int32 or int64 words, auto-detected
    // d_in[3] = side (constant 32), unused.
    float* out = (float*)d_out;

    main_kernel<<<GRIDM, 256>>>(d, m, poi, out);
}